// round 12
// baseline (speedup 1.0000x reference)
#include <cuda_runtime.h>
#include <math.h>

#define HH 112
#define WW 112
#define NPIX (HH*WW)          // 12544
#define GRID 7
#define NCELL 49
#define NFEAT 1822
#define BMAX 1024
#define TWO_PI_F 6.283185307179586f

// ---- scratch (static device arrays; no cudaMalloc anywhere) ----
__device__ float d_gray[(size_t)BMAX * NPIX];
__device__ unsigned long long d_tmp[(size_t)BMAX * NPIX];   // f32x2 interleaved (o0,o1)
__device__ float d_part[(size_t)BMAX * NCELL * 9];

// ---- f32x2 packed helpers (sm_100+) ----
__device__ __forceinline__ unsigned long long pk2(float a, float b) {
    unsigned long long r;
    asm("mov.b64 %0, {%1, %2};" : "=l"(r) : "f"(a), "f"(b));
    return r;
}
__device__ __forceinline__ unsigned long long fma2(unsigned long long a,
                                                   unsigned long long b,
                                                   unsigned long long c) {
    unsigned long long d;
    asm("fma.rn.f32x2 %0, %1, %2, %3;" : "=l"(d) : "l"(a), "l"(b), "l"(c));
    return d;
}
__device__ __forceinline__ void upk2(unsigned long long v, float& lo, float& hi) {
    asm("mov.b64 {%0, %1}, %2;" : "=f"(lo), "=f"(hi) : "l"(v));
}
__device__ __forceinline__ unsigned int redux_add_u32(unsigned int v) {
    unsigned int r;
    asm("redux.sync.add.u32 %0, %1, 0xffffffff;" : "=r"(r) : "r"(v));
    return r;
}

// =====================================================================
// Kernel 1: per-cell features, warp-per-cell. block = 224 (7 warps),
// grid = (7, B): blockIdx.x = cell row cy, warp = cell col cx.
// Each thread: 8 px (2 rows x 4 cols via float4). No __syncthreads.
// =====================================================================
__global__ void __launch_bounds__(224) cell_kernel(const float* __restrict__ img,
                                                   float* __restrict__ out)
{
    __shared__ float tile[7][18][19];
    __shared__ float stot[7][16];

    const int cy   = blockIdx.x;
    const int b    = blockIdx.y;
    const int tid  = threadIdx.x;
    const int lane = tid & 31;
    const int cx   = tid >> 5;          // warp id = cell col
    const int cell = cy * GRID + cx;

    const float* base = img + (size_t)b * 3 * NPIX;
    const int oy = cy * 16 - 1;
    const int ox = cx * 16 - 1;

    const int cg  = lane & 3;           // col group (4 cols)
    const int rp  = lane >> 2;          // row pair 0..7
    const int gx0 = cx * 16 + cg * 4;
    const int r0  = rp * 2;             // local rows r0, r0+1
    const int gy0 = cy * 16 + r0;

    float (*tw)[19] = tile[cx];

    // ---- load 8 px (2 rows x float4 x 3 channels) ----
    float Rv[8], Gv[8], Bv[8];
    {
        const int p0 = gy0 * WW + gx0;
        float4 ra = *reinterpret_cast<const float4*>(base + p0);
        float4 rb = *reinterpret_cast<const float4*>(base + p0 + WW);
        float4 ga = *reinterpret_cast<const float4*>(base + NPIX + p0);
        float4 gb = *reinterpret_cast<const float4*>(base + NPIX + p0 + WW);
        float4 ba = *reinterpret_cast<const float4*>(base + 2 * NPIX + p0);
        float4 bb = *reinterpret_cast<const float4*>(base + 2 * NPIX + p0 + WW);
        Rv[0]=ra.x; Rv[1]=ra.y; Rv[2]=ra.z; Rv[3]=ra.w;
        Rv[4]=rb.x; Rv[5]=rb.y; Rv[6]=rb.z; Rv[7]=rb.w;
        Gv[0]=ga.x; Gv[1]=ga.y; Gv[2]=ga.z; Gv[3]=ga.w;
        Gv[4]=gb.x; Gv[5]=gb.y; Gv[6]=gb.z; Gv[7]=gb.w;
        Bv[0]=ba.x; Bv[1]=ba.y; Bv[2]=ba.z; Bv[3]=ba.w;
        Bv[4]=bb.x; Bv[5]=bb.y; Bv[6]=bb.z; Bv[7]=bb.w;

        float gr[8];
        #pragma unroll
        for (int j = 0; j < 8; j++)
            gr[j] = 0.299f * Rv[j] + 0.587f * Gv[j] + 0.114f * Bv[j];
        #pragma unroll
        for (int j = 0; j < 4; j++) {
            tw[r0 + 1][cg * 4 + 1 + j] = gr[j];
            tw[r0 + 2][cg * 4 + 1 + j] = gr[4 + j];
        }
        float4 g0 = make_float4(gr[0], gr[1], gr[2], gr[3]);
        float4 g1 = make_float4(gr[4], gr[5], gr[6], gr[7]);
        *reinterpret_cast<float4*>(d_gray + (size_t)b * NPIX + p0)      = g0;
        *reinterpret_cast<float4*>(d_gray + (size_t)b * NPIX + p0 + WW) = g1;
    }

    // halo: 68 perimeter positions, coords clamped (clamp == edge pad)
    for (int i = lane; i < 68; i += 32) {
        int rr, cc;
        if (i < 18)      { rr = 0;          cc = i; }
        else if (i < 36) { rr = 17;         cc = i - 18; }
        else if (i < 52) { rr = i - 36 + 1; cc = 0; }
        else             { rr = i - 52 + 1; cc = 17; }
        int yy = min(max(oy + rr, 0), HH - 1);
        int xx = min(max(ox + cc, 0), WW - 1);
        int pp = yy * WW + xx;
        tw[rr][cc] = 0.299f * base[pp] + 0.587f * base[NPIX + pp] + 0.114f * base[2 * NPIX + pp];
    }
    __syncwarp();

    float acc[15];
    #pragma unroll
    for (int k = 0; k < 15; k++) acc[k] = 0.0f;

    // ---- Pass A: histogram (nibble regs) + HSV ----
    unsigned int hR = 0, hG = 0, hB = 0;
    #pragma unroll
    for (int j = 0; j < 8; j++) {
        const float rr = Rv[j], gg = Gv[j], bb = Bv[j];
        int ir = (int)floorf(rr * 8.0f); if ((unsigned)ir < 8u) hR += 1u << (ir << 2);
        int ig = (int)floorf(gg * 8.0f); if ((unsigned)ig < 8u) hG += 1u << (ig << 2);
        int ib = (int)floorf(bb * 8.0f); if ((unsigned)ib < 8u) hB += 1u << (ib << 2);

        float maxc = fmaxf(rr, fmaxf(gg, bb));
        float minc = fminf(rr, fminf(gg, bb));
        float vv = maxc;
        float delta = maxc - minc;
        float dsafe = (delta == 0.0f) ? 1.0f : delta;
        float me = maxc + 1e-8f;
        float inv = __fdividef(1.0f, me * dsafe);
        float ss = delta * dsafe * inv;
        float invd = me * inv;
        float rc = (maxc - rr) * invd;
        float gc = (maxc - gg) * invd;
        float bc = (maxc - bb) * invd;
        float hh;
        if (maxc == rr)      hh = bc - gc;
        else if (maxc == gg) hh = 2.0f + rc - bc;
        else                 hh = 4.0f + gc - rc;
        hh = hh * (1.0f / 6.0f);
        hh = hh - floorf(hh);
        hh = hh * TWO_PI_F;

        acc[0] += rr; acc[1] += gg; acc[2] += bb;
        acc[3] += hh; acc[4] += ss; acc[5] += vv;
        acc[6] += hh * hh; acc[7] += ss * ss; acc[8] += vv * vv;
    }

    // ---- Pass B: Sobel (clamp via halo) + Laplacian (reflect) ----
    {
        float w[4][6];
        #pragma unroll
        for (int i = 0; i < 4; i++)
            #pragma unroll
            for (int c = 0; c < 6; c++)
                w[i][c] = tw[r0 + i][cg * 4 + c];

        const bool eL = (gx0 == 0), eR = (gx0 == WW - 4);
        #pragma unroll
        for (int k = 0; k < 2; k++) {
            const int gy = gy0 + k;
            const bool eT = (gy == 0), eB = (gy == HH - 1);
            float colS[6], dd[6], lapTB[6];
            #pragma unroll
            for (int c = 0; c < 6; c++) {
                colS[c]  = w[k][c] + 2.0f * w[k+1][c] + w[k+2][c];
                dd[c]    = w[k+2][c] - w[k][c];
                lapTB[c] = (eT ? w[k+2][c] : w[k][c]) + (eB ? w[k][c] : w[k+2][c]);
            }
            #pragma unroll
            for (int j = 0; j < 4; j++) {
                float gxv = 0.125f * (colS[j + 2] - colS[j]);
                float gyv = 0.125f * (dd[j] + 2.0f * dd[j + 1] + dd[j + 2]);
                float d2  = gxv * gxv + gyv * gyv;
                float mag = sqrtf(d2 + 1e-8f);
                float ca  = (d2 > 0.0f) ? gxv * rsqrtf(d2) : 1.0f;

                float vL  = (eL && j == 0) ? lapTB[j + 2] : lapTB[j];
                float w1L = (eL && j == 0) ? w[k+1][j + 2] : w[k+1][j];
                float vR  = (eR && j == 3) ? lapTB[j] : lapTB[j + 2];
                float w1R = (eR && j == 3) ? w[k+1][j] : w[k+1][j + 2];
                float nb  = vL + lapTB[j + 1] + vR + w1L + w1R;
                float lap = nb * 0.0625f - 0.5f * w[k+1][j + 1];

                acc[9]  += mag; acc[10] += mag * mag; acc[11] += ca;
                acc[12] += lap; acc[13] += lap * lap; acc[14] += fabsf(lap);
            }
        }
    }

    // ---- histogram: nibble -> 16-bit fields -> redux ----
    unsigned int h16[12];
    h16[0] = (hR & 0xFu)         | ((hR << 12) & 0xF0000u);
    h16[1] = ((hR >> 8)  & 0xFu) | ((hR << 4)  & 0xF0000u);
    h16[2] = ((hR >> 16) & 0xFu) | ((hR >> 4)  & 0xF0000u);
    h16[3] = ((hR >> 24) & 0xFu) | ((hR >> 12) & 0xF0000u);
    h16[4] = (hG & 0xFu)         | ((hG << 12) & 0xF0000u);
    h16[5] = ((hG >> 8)  & 0xFu) | ((hG << 4)  & 0xF0000u);
    h16[6] = ((hG >> 16) & 0xFu) | ((hG >> 4)  & 0xF0000u);
    h16[7] = ((hG >> 24) & 0xFu) | ((hG >> 12) & 0xF0000u);
    h16[8] = (hB & 0xFu)         | ((hB << 12) & 0xF0000u);
    h16[9] = ((hB >> 8)  & 0xFu) | ((hB << 4)  & 0xF0000u);
    h16[10]= ((hB >> 16) & 0xFu) | ((hB >> 4)  & 0xF0000u);
    h16[11]= ((hB >> 24) & 0xFu) | ((hB >> 12) & 0xF0000u);
    #pragma unroll
    for (int k = 0; k < 12; k++) h16[k] = redux_add_u32(h16[k]);

    float* ob = out + (size_t)b * NFEAT;
    if (lane < 24) {
        unsigned int pick = 0;
        #pragma unroll
        for (int j = 0; j < 12; j++)
            if ((lane >> 1) == j) pick = h16[j];
        unsigned int cnt = (pick >> (16 * (lane & 1))) & 0xFFFFu;
        ob[3 + ((size_t)cell * 3 + (lane >> 3)) * 8 + (lane & 7)] = (float)cnt * (1.0f / 256.0f);
    }

    // ---- 15 float warp reductions ----
    #pragma unroll
    for (int k = 0; k < 15; k++) {
        float x = acc[k];
        #pragma unroll
        for (int o = 16; o > 0; o >>= 1) x += __shfl_down_sync(0xffffffffu, x, o);
        if (lane == 0) stot[cx][k] = x;
    }
    __syncwarp();

    if (lane < 9) d_part[((size_t)b * NCELL + cell) * 9 + lane] = stot[cx][lane];
    if (lane >= 9 && lane < 12) ob[1185 + cell * 3 + (lane - 9)] = stot[cx][lane - 6] * (1.0f / 256.0f);
    if (lane == 12) {
        float sm = stot[cx][9], sq = stot[cx][10];
        ob[1332 + cell * 4 + 0] = sm * (1.0f / 256.0f);
        ob[1332 + cell * 4 + 1] = sqrtf(fmaxf(0.0f, (sq - sm * sm * (1.0f / 256.0f)) * (1.0f / 255.0f)));
        ob[1332 + cell * 4 + 2] = sq * (1.0f / 256.0f);
        ob[1332 + cell * 4 + 3] = stot[cx][11] * (1.0f / 256.0f);
    }
    if (lane == 13) {
        float lm = stot[cx][12], lq = stot[cx][13];
        ob[1528 + cell * 4 + 0] = lm * (1.0f / 256.0f);
        ob[1528 + cell * 4 + 1] = sqrtf(fmaxf(0.0f, (lq - lm * lm * (1.0f / 256.0f)) * (1.0f / 255.0f)));
        ob[1528 + cell * 4 + 2] = lq * (1.0f / 256.0f);
        ob[1528 + cell * 4 + 3] = stot[cx][14] * (1.0f / 256.0f);
    }
}

// =====================================================================
// Kernel 2: horizontal Gabor pass, both orientations packed (f32x2).
// block = 128 threads = 8 rows x 16 groups of 7 outputs. grid = B*14.
// Writes interleaved u64 tmp to DRAM.
// =====================================================================
__global__ void __launch_bounds__(128) gabor_h(const float* __restrict__ gk0,
                                               const float* __restrict__ gk1)
{
    __shared__ float srow[8][136];     // data at cols 12..123, zero halo 2..11 / 124..133
    const int tid  = threadIdx.x;
    const int row0 = blockIdx.x * 8;

    unsigned long long tapH[21];
    #pragma unroll
    for (int d = 0; d < 21; d++)
        tapH[d] = pk2(__ldg(&gk0[210 + d]), __ldg(&gk1[210 + d]));

    for (int i = tid; i < 160; i += 128) {
        int rr = i / 20, c = i % 20;
        srow[rr][(c < 10) ? (2 + c) : (114 + c)] = 0.0f;
    }
    const float* gr = d_gray + (size_t)row0 * WW;
    for (int i = tid; i < 8 * 28; i += 128) {
        int r = i / 28, j = i % 28;
        float4 v = *reinterpret_cast<const float4*>(gr + r * WW + 4 * j);
        *reinterpret_cast<float4*>(&srow[r][12 + 4 * j]) = v;
    }
    __syncthreads();

    const int row = tid >> 4, xg = tid & 15;
    const float* bp = &srow[row][2 + xg * 7];
    unsigned long long a[7];
    #pragma unroll
    for (int i = 0; i < 7; i++) a[i] = 0ULL;
    #pragma unroll
    for (int k = 0; k < 27; k++) {
        float v = bp[k];
        unsigned long long vp = pk2(v, v);
        #pragma unroll
        for (int i = 0; i < 7; i++) {
            int d = k - i;
            if (d >= 0 && d < 21) a[i] = fma2(tapH[d], vp, a[i]);
        }
    }
    unsigned long long* o = d_tmp + (size_t)(row0 + row) * WW + xg * 7;
    #pragma unroll
    for (int i = 0; i < 7; i++) o[i] = a[i];
}

// =====================================================================
// Kernel 3: vertical Gabor pass + |.| + per-cell means (+ per-image
// finalize on strip 0). block = 224 = 16 cols x 14 y-groups of 8.
// grid = (7, B). Warp w == cell row w (one warp reduction per cell).
// s row stride 17 u64 -> half-warps hit disjoint bank sets.
// =====================================================================
__global__ void __launch_bounds__(224) gabor_v(const float* __restrict__ gk0,
                                               const float* __restrict__ gk1,
                                               float* __restrict__ out)
{
    __shared__ unsigned long long s[132 * 17];
    __shared__ float fin[9];

    const int cx  = blockIdx.x;
    const int b   = blockIdx.y;
    const int tid = threadIdx.x;
    const int lane = tid & 31;

    unsigned long long tapV[21];
    {
        float inv0 = __fdividef(1.0f, __ldg(&gk0[220]));
        float inv1 = __fdividef(1.0f, __ldg(&gk1[220]));
        #pragma unroll
        for (int d = 0; d < 21; d++)
            tapV[d] = pk2(__ldg(&gk0[d * 21 + 10]) * inv0,
                          __ldg(&gk1[d * 21 + 10]) * inv1);
    }

    const int x0 = cx * 16;
    const unsigned long long* t = d_tmp + (size_t)b * NPIX;
    for (int i = tid; i < 132 * 16; i += 224) {
        int rr = i >> 4, cc = i & 15;
        int yy = rr - 10;
        s[rr * 17 + cc] = (yy >= 0 && yy < HH) ? t[yy * WW + x0 + cc] : 0ULL;
    }
    __syncthreads();

    const int x = tid & 15, ty = tid >> 4, yb = ty * 8;
    unsigned long long a[8];
    #pragma unroll
    for (int j = 0; j < 8; j++) a[j] = 0ULL;
    #pragma unroll
    for (int k = 0; k < 28; k++) {
        unsigned long long vp = s[(yb + k) * 17 + x];
        #pragma unroll
        for (int j = 0; j < 8; j++) {
            int d = k - j;
            if (d >= 0 && d < 21) a[j] = fma2(tapV[d], vp, a[j]);
        }
    }
    float s0 = 0.0f, s1 = 0.0f;
    #pragma unroll
    for (int j = 0; j < 8; j++) {
        float lo, hi;
        upk2(a[j], lo, hi);
        s0 += fabsf(lo);
        s1 += fabsf(hi);
    }
    #pragma unroll
    for (int o = 16; o > 0; o >>= 1) {
        s0 += __shfl_down_sync(0xffffffffu, s0, o);
        s1 += __shfl_down_sync(0xffffffffu, s1, o);
    }
    float* ob = out + (size_t)b * NFEAT;
    if (lane == 0) {
        int w = tid >> 5;                 // cell row
        ob[1724 + w * GRID + cx] = s0 * (1.0f / 256.0f);
        ob[1773 + w * GRID + cx] = s1 * (1.0f / 256.0f);
    }

    // per-image finalize (strip 0 only), warp 0 lanes 0..15
    if (cx == 0 && tid < 16) {
        if (tid < 9) {
            const float* pp = d_part + (size_t)b * NCELL * 9;
            float sI = 0.0f;
            for (int c = 0; c < NCELL; c++) sI += pp[c * 9 + tid];
            fin[tid] = sI;
        }
        __syncwarp(0xffffu);
        if (tid == 0) {
            const float N = (float)NPIX;
            ob[0] = fin[0] / N;
            ob[1] = fin[1] / N;
            ob[2] = fin[2] / N;
            #pragma unroll
            for (int k = 0; k < 3; k++) {
                float smv = fin[3 + k];
                float sqv = fin[6 + k];
                float var = (sqv - smv * smv / N) / (N - 1.0f);
                ob[1179 + 2 * k] = smv / N;
                ob[1180 + 2 * k] = sqrtf(fmaxf(var, 0.0f));
            }
        }
    }
}

// =====================================================================
extern "C" void kernel_launch(void* const* d_in, const int* in_sizes, int n_in,
                              void* d_out, int out_size)
{
    const float* img = (const float*)d_in[0];
    const float* gk0 = (const float*)d_in[1];
    const float* gk1 = (const float*)d_in[2];
    float* out = (float*)d_out;

    int B = in_sizes[0] / (3 * NPIX);
    if (B > BMAX) B = BMAX;

    cell_kernel<<<dim3(GRID, B), 224>>>(img, out);
    gabor_h<<<B * (HH / 8), 128>>>(gk0, gk1);
    gabor_v<<<dim3(GRID, B), 224>>>(gk0, gk1, out);
}

// round 14
// speedup vs baseline: 1.0664x; 1.0664x over previous
#include <cuda_runtime.h>
#include <math.h>

#define HH 112
#define WW 112
#define NPIX (HH*WW)          // 12544
#define GRID 7
#define NCELL 49
#define NFEAT 1822
#define BMAX 1024
#define TWO_PI_F 6.283185307179586f

// ---- scratch (static device arrays; no cudaMalloc anywhere) ----
__device__ float d_gray[(size_t)BMAX * NPIX];
__device__ float d_part[(size_t)BMAX * NCELL * 9];

// ---- f32x2 packed helpers (sm_100+) ----
__device__ __forceinline__ unsigned long long pk2(float a, float b) {
    unsigned long long r;
    asm("mov.b64 %0, {%1, %2};" : "=l"(r) : "f"(a), "f"(b));
    return r;
}
__device__ __forceinline__ unsigned long long fma2(unsigned long long a,
                                                   unsigned long long b,
                                                   unsigned long long c) {
    unsigned long long d;
    asm("fma.rn.f32x2 %0, %1, %2, %3;" : "=l"(d) : "l"(a), "l"(b), "l"(c));
    return d;
}
__device__ __forceinline__ void upk2(unsigned long long v, float& lo, float& hi) {
    asm("mov.b64 {%0, %1}, %2;" : "=f"(lo), "=f"(hi) : "l"(v));
}
__device__ __forceinline__ unsigned int redux_add_u32(unsigned int v) {
    unsigned int r;
    asm("redux.sync.add.u32 %0, %1, 0xffffffff;" : "=r"(r) : "r"(v));
    return r;
}

// =====================================================================
// Kernel 1: per-cell features, warp-per-cell. block = 224 (7 warps),
// grid = (7, B). Each thread: 8 px. Per-row-pair processing keeps only
// 12 channel regs live; launch_bounds(224,4) -> 4 blocks/SM.
// =====================================================================
__global__ void __launch_bounds__(224, 4) cell_kernel(const float* __restrict__ img,
                                                      float* __restrict__ out)
{
    __shared__ float tile[7][18][19];
    __shared__ float stot[7][16];

    const int cy   = blockIdx.x;
    const int b    = blockIdx.y;
    const int tid  = threadIdx.x;
    const int lane = tid & 31;
    const int cx   = tid >> 5;          // warp id = cell col
    const int cell = cy * GRID + cx;

    const float* base = img + (size_t)b * 3 * NPIX;
    const int oy = cy * 16 - 1;
    const int ox = cx * 16 - 1;

    const int cg  = lane & 3;           // col group (4 cols)
    const int rp  = lane >> 2;          // row pair 0..7
    const int gx0 = cx * 16 + cg * 4;
    const int r0  = rp * 2;             // local rows r0, r0+1
    const int gy0 = cy * 16 + r0;

    float (*tw)[19] = tile[cx];

    float acc[15];
    #pragma unroll
    for (int k = 0; k < 15; k++) acc[k] = 0.0f;
    unsigned int hR = 0, hG = 0, hB = 0;

    // ---- per-row-pair: load float4 RGB, gray, histogram, HSV ----
    #pragma unroll
    for (int q = 0; q < 2; q++) {
        const int p = (gy0 + q) * WW + gx0;
        float4 r4 = *reinterpret_cast<const float4*>(base + p);
        float4 g4 = *reinterpret_cast<const float4*>(base + NPIX + p);
        float4 b4 = *reinterpret_cast<const float4*>(base + 2 * NPIX + p);
        float R[4]  = {r4.x, r4.y, r4.z, r4.w};
        float Gc[4] = {g4.x, g4.y, g4.z, g4.w};
        float Bl[4] = {b4.x, b4.y, b4.z, b4.w};

        float gr[4];
        #pragma unroll
        for (int j = 0; j < 4; j++) {
            gr[j] = 0.299f * R[j] + 0.587f * Gc[j] + 0.114f * Bl[j];
            tw[r0 + 1 + q][cg * 4 + 1 + j] = gr[j];
        }
        float4 go = make_float4(gr[0], gr[1], gr[2], gr[3]);
        *reinterpret_cast<float4*>(d_gray + (size_t)b * NPIX + p) = go;

        #pragma unroll
        for (int j = 0; j < 4; j++) {
            const float rr = R[j], gg = Gc[j], bb = Bl[j];
            int ir = __float2int_rd(rr * 8.0f); if ((unsigned)ir < 8u) hR += 1u << (ir << 2);
            int ig = __float2int_rd(gg * 8.0f); if ((unsigned)ig < 8u) hG += 1u << (ig << 2);
            int ib = __float2int_rd(bb * 8.0f); if ((unsigned)ib < 8u) hB += 1u << (ib << 2);

            float maxc = fmaxf(rr, fmaxf(gg, bb));
            float minc = fminf(rr, fminf(gg, bb));
            float vv = maxc;
            float delta = maxc - minc;
            float dsafe = (delta == 0.0f) ? 1.0f : delta;
            float me = maxc + 1e-8f;
            float inv = __fdividef(1.0f, me * dsafe);
            float ss = delta * dsafe * inv;
            float invd = me * inv;
            float rc = (maxc - rr) * invd;
            float gc = (maxc - gg) * invd;
            float bc = (maxc - bb) * invd;
            float hh;
            if (maxc == rr)      hh = bc - gc;
            else if (maxc == gg) hh = 2.0f + rc - bc;
            else                 hh = 4.0f + gc - rc;
            hh = hh * (1.0f / 6.0f);
            hh = hh - floorf(hh);
            hh = hh * TWO_PI_F;

            acc[0] += rr; acc[1] += gg; acc[2] += bb;
            acc[3] += hh; acc[4] += ss; acc[5] += vv;
            acc[6] += hh * hh; acc[7] += ss * ss; acc[8] += vv * vv;
        }
    }

    // halo: 68 perimeter positions, coords clamped (clamp == edge pad)
    for (int i = lane; i < 68; i += 32) {
        int rr, cc;
        if (i < 18)      { rr = 0;          cc = i; }
        else if (i < 36) { rr = 17;         cc = i - 18; }
        else if (i < 52) { rr = i - 36 + 1; cc = 0; }
        else             { rr = i - 52 + 1; cc = 17; }
        int yy = min(max(oy + rr, 0), HH - 1);
        int xx = min(max(ox + cc, 0), WW - 1);
        int pp = yy * WW + xx;
        tw[rr][cc] = 0.299f * base[pp] + 0.587f * base[NPIX + pp] + 0.114f * base[2 * NPIX + pp];
    }
    __syncwarp();

    // ---- Sobel (clamp via halo) + Laplacian (reflect) ----
    {
        float w[4][6];
        #pragma unroll
        for (int i = 0; i < 4; i++)
            #pragma unroll
            for (int c = 0; c < 6; c++)
                w[i][c] = tw[r0 + i][cg * 4 + c];

        const bool eL = (gx0 == 0), eR = (gx0 == WW - 4);
        #pragma unroll
        for (int k = 0; k < 2; k++) {
            const int gy = gy0 + k;
            const bool eT = (gy == 0), eB = (gy == HH - 1);
            float colS[6], dd[6], lapTB[6];
            #pragma unroll
            for (int c = 0; c < 6; c++) {
                colS[c]  = w[k][c] + 2.0f * w[k+1][c] + w[k+2][c];
                dd[c]    = w[k+2][c] - w[k][c];
                lapTB[c] = (eT ? w[k+2][c] : w[k][c]) + (eB ? w[k][c] : w[k+2][c]);
            }
            #pragma unroll
            for (int j = 0; j < 4; j++) {
                float gxv = 0.125f * (colS[j + 2] - colS[j]);
                float gyv = 0.125f * (dd[j] + 2.0f * dd[j + 1] + dd[j + 2]);
                float d2  = gxv * gxv + gyv * gyv;
                float mag = sqrtf(d2 + 1e-8f);
                float ca  = (d2 > 0.0f) ? gxv * rsqrtf(d2) : 1.0f;

                float vL  = (eL && j == 0) ? lapTB[j + 2] : lapTB[j];
                float w1L = (eL && j == 0) ? w[k+1][j + 2] : w[k+1][j];
                float vR  = (eR && j == 3) ? lapTB[j] : lapTB[j + 2];
                float w1R = (eR && j == 3) ? w[k+1][j] : w[k+1][j + 2];
                float nb  = vL + lapTB[j + 1] + vR + w1L + w1R;
                float lap = nb * 0.0625f - 0.5f * w[k+1][j + 1];

                acc[9]  += mag; acc[10] += mag * mag; acc[11] += ca;
                acc[12] += lap; acc[13] += lap * lap; acc[14] += fabsf(lap);
            }
        }
    }

    // ---- histogram: nibble -> 16-bit fields -> redux ----
    unsigned int h16[12];
    h16[0] = (hR & 0xFu)         | ((hR << 12) & 0xF0000u);
    h16[1] = ((hR >> 8)  & 0xFu) | ((hR << 4)  & 0xF0000u);
    h16[2] = ((hR >> 16) & 0xFu) | ((hR >> 4)  & 0xF0000u);
    h16[3] = ((hR >> 24) & 0xFu) | ((hR >> 12) & 0xF0000u);
    h16[4] = (hG & 0xFu)         | ((hG << 12) & 0xF0000u);
    h16[5] = ((hG >> 8)  & 0xFu) | ((hG << 4)  & 0xF0000u);
    h16[6] = ((hG >> 16) & 0xFu) | ((hG >> 4)  & 0xF0000u);
    h16[7] = ((hG >> 24) & 0xFu) | ((hG >> 12) & 0xF0000u);
    h16[8] = (hB & 0xFu)         | ((hB << 12) & 0xF0000u);
    h16[9] = ((hB >> 8)  & 0xFu) | ((hB << 4)  & 0xF0000u);
    h16[10]= ((hB >> 16) & 0xFu) | ((hB >> 4)  & 0xF0000u);
    h16[11]= ((hB >> 24) & 0xFu) | ((hB >> 12) & 0xF0000u);
    #pragma unroll
    for (int k = 0; k < 12; k++) h16[k] = redux_add_u32(h16[k]);

    float* ob = out + (size_t)b * NFEAT;
    if (lane < 24) {
        unsigned int pick = 0;
        #pragma unroll
        for (int j = 0; j < 12; j++)
            if ((lane >> 1) == j) pick = h16[j];
        unsigned int cnt = (pick >> (16 * (lane & 1))) & 0xFFFFu;
        ob[3 + ((size_t)cell * 3 + (lane >> 3)) * 8 + (lane & 7)] = (float)cnt * (1.0f / 256.0f);
    }

    // ---- 15 float warp reductions ----
    #pragma unroll
    for (int k = 0; k < 15; k++) {
        float x = acc[k];
        #pragma unroll
        for (int o = 16; o > 0; o >>= 1) x += __shfl_down_sync(0xffffffffu, x, o);
        if (lane == 0) stot[cx][k] = x;
    }
    __syncwarp();

    if (lane < 9) d_part[((size_t)b * NCELL + cell) * 9 + lane] = stot[cx][lane];
    if (lane >= 9 && lane < 12) ob[1185 + cell * 3 + (lane - 9)] = stot[cx][lane - 6] * (1.0f / 256.0f);
    if (lane == 12) {
        float sm = stot[cx][9], sq = stot[cx][10];
        ob[1332 + cell * 4 + 0] = sm * (1.0f / 256.0f);
        ob[1332 + cell * 4 + 1] = sqrtf(fmaxf(0.0f, (sq - sm * sm * (1.0f / 256.0f)) * (1.0f / 255.0f)));
        ob[1332 + cell * 4 + 2] = sq * (1.0f / 256.0f);
        ob[1332 + cell * 4 + 3] = stot[cx][11] * (1.0f / 256.0f);
    }
    if (lane == 13) {
        float lm = stot[cx][12], lq = stot[cx][13];
        ob[1528 + cell * 4 + 0] = lm * (1.0f / 256.0f);
        ob[1528 + cell * 4 + 1] = sqrtf(fmaxf(0.0f, (lq - lm * lm * (1.0f / 256.0f)) * (1.0f / 255.0f)));
        ob[1528 + cell * 4 + 2] = lq * (1.0f / 256.0f);
        ob[1528 + cell * 4 + 3] = stot[cx][14] * (1.0f / 256.0f);
    }
}

// =====================================================================
// Kernel 2: strip-fused Gabor. One block per (image, 16-col strip):
// h-pass for the strip's 16 output cols (reads gray cols x0-10..x0+25),
// then v-pass + |.| + per-cell means, all in smem. No DRAM tmp.
// block = 224, grid = (7, B). f32x2 packs both orientations.
// =====================================================================
__global__ void __launch_bounds__(224, 4) gabor_strip(const float* __restrict__ gk0,
                                                      const float* __restrict__ gk1,
                                                      float* __restrict__ out)
{
    __shared__ float sgs[112 * 37];                // gray strip, 36 cols + pad
    __shared__ unsigned long long t2[132 * 17];    // h result, 10-row zero halo
    __shared__ float fin[9];

    const int cx   = blockIdx.x;
    const int b    = blockIdx.y;
    const int tid  = threadIdx.x;
    const int lane = tid & 31;
    const int x0   = cx * 16;

    unsigned long long tapH[21];
    #pragma unroll
    for (int d = 0; d < 21; d++)
        tapH[d] = pk2(__ldg(&gk0[210 + d]), __ldg(&gk1[210 + d]));

    // zero t2 halo rows (0..9, 122..131)
    for (int i = tid; i < 20 * 16; i += 224) {
        int rr = i >> 4, cc = i & 15;
        int row = (rr < 10) ? rr : rr + 112;
        t2[row * 17 + cc] = 0ULL;
    }
    // load gray strip: cols x0-10 .. x0+25, zero outside image
    const float* gr = d_gray + (size_t)b * NPIX;
    for (int i = tid; i < 112 * 36; i += 224) {
        int row = i / 36, lc = i % 36;
        int gx = x0 - 10 + lc;
        sgs[row * 37 + lc] = (gx >= 0 && gx < WW) ? gr[row * WW + gx] : 0.0f;
    }
    __syncthreads();

    // ---- h-pass: thread = (row, half); 8 outputs each ----
    {
        const int row  = (tid < 112) ? tid : tid - 112;
        const int j0   = (tid < 112) ? 0 : 8;
        const float* bp = sgs + row * 37 + j0;
        unsigned long long a[8];
        #pragma unroll
        for (int i = 0; i < 8; i++) a[i] = 0ULL;
        #pragma unroll
        for (int k = 0; k < 28; k++) {
            float v = bp[k];
            unsigned long long vp = pk2(v, v);
            #pragma unroll
            for (int i = 0; i < 8; i++) {
                int d = k - i;
                if (d >= 0 && d < 21) a[i] = fma2(tapH[d], vp, a[i]);
            }
        }
        unsigned long long* o = t2 + (row + 10) * 17 + j0;
        #pragma unroll
        for (int i = 0; i < 8; i++) o[i] = a[i];
    }

    unsigned long long tapV[21];
    {
        float inv0 = __fdividef(1.0f, __ldg(&gk0[220]));
        float inv1 = __fdividef(1.0f, __ldg(&gk1[220]));
        #pragma unroll
        for (int d = 0; d < 21; d++)
            tapV[d] = pk2(__ldg(&gk0[d * 21 + 10]) * inv0,
                          __ldg(&gk1[d * 21 + 10]) * inv1);
    }
    __syncthreads();

    // ---- v-pass: 16 cols x 14 y-groups of 8; warp w == cell row w ----
    const int x = tid & 15, ty = tid >> 4, yb = ty * 8;
    unsigned long long a[8];
    #pragma unroll
    for (int j = 0; j < 8; j++) a[j] = 0ULL;
    #pragma unroll
    for (int k = 0; k < 28; k++) {
        unsigned long long vp = t2[(yb + k) * 17 + x];
        #pragma unroll
        for (int j = 0; j < 8; j++) {
            int d = k - j;
            if (d >= 0 && d < 21) a[j] = fma2(tapV[d], vp, a[j]);
        }
    }
    float s0 = 0.0f, s1 = 0.0f;
    #pragma unroll
    for (int j = 0; j < 8; j++) {
        float lo, hi;
        upk2(a[j], lo, hi);
        s0 += fabsf(lo);
        s1 += fabsf(hi);
    }
    #pragma unroll
    for (int o = 16; o > 0; o >>= 1) {
        s0 += __shfl_down_sync(0xffffffffu, s0, o);
        s1 += __shfl_down_sync(0xffffffffu, s1, o);
    }
    float* ob = out + (size_t)b * NFEAT;
    if (lane == 0) {
        int w = tid >> 5;                 // cell row
        ob[1724 + w * GRID + cx] = s0 * (1.0f / 256.0f);
        ob[1773 + w * GRID + cx] = s1 * (1.0f / 256.0f);
    }

    // per-image finalize (strip 0 only), warp 0 lanes 0..15
    if (cx == 0 && tid < 16) {
        if (tid < 9) {
            const float* pp = d_part + (size_t)b * NCELL * 9;
            float sI = 0.0f;
            for (int c = 0; c < NCELL; c++) sI += pp[c * 9 + tid];
            fin[tid] = sI;
        }
        __syncwarp(0xffffu);
        if (tid == 0) {
            const float N = (float)NPIX;
            ob[0] = fin[0] / N;
            ob[1] = fin[1] / N;
            ob[2] = fin[2] / N;
            #pragma unroll
            for (int k = 0; k < 3; k++) {
                float smv = fin[3 + k];
                float sqv = fin[6 + k];
                float var = (sqv - smv * smv / N) / (N - 1.0f);
                ob[1179 + 2 * k] = smv / N;
                ob[1180 + 2 * k] = sqrtf(fmaxf(var, 0.0f));
            }
        }
    }
}

// =====================================================================
extern "C" void kernel_launch(void* const* d_in, const int* in_sizes, int n_in,
                              void* d_out, int out_size)
{
    const float* img = (const float*)d_in[0];
    const float* gk0 = (const float*)d_in[1];
    const float* gk1 = (const float*)d_in[2];
    float* out = (float*)d_out;

    int B = in_sizes[0] / (3 * NPIX);
    if (B > BMAX) B = BMAX;

    cell_kernel<<<dim3(GRID, B), 224>>>(img, out);
    gabor_strip<<<dim3(GRID, B), 224>>>(gk0, gk1, out);
}

// round 15
// speedup vs baseline: 1.1777x; 1.1043x over previous
#include <cuda_runtime.h>
#include <math.h>

#define HH 112
#define WW 112
#define NPIX (HH*WW)          // 12544
#define GRID 7
#define NCELL 49
#define NFEAT 1822
#define BMAX 1024
#define TWO_PI_F 6.283185307179586f

// ---- scratch (static device arrays; no cudaMalloc anywhere) ----
__device__ float d_part[(size_t)BMAX * NCELL * 9];

// ---- f32x2 packed helpers (sm_100+) ----
__device__ __forceinline__ unsigned long long pk2(float a, float b) {
    unsigned long long r;
    asm("mov.b64 %0, {%1, %2};" : "=l"(r) : "f"(a), "f"(b));
    return r;
}
__device__ __forceinline__ unsigned long long fma2(unsigned long long a,
                                                   unsigned long long b,
                                                   unsigned long long c) {
    unsigned long long d;
    asm("fma.rn.f32x2 %0, %1, %2, %3;" : "=l"(d) : "l"(a), "l"(b), "l"(c));
    return d;
}
__device__ __forceinline__ void upk2(unsigned long long v, float& lo, float& hi) {
    asm("mov.b64 {%0, %1}, %2;" : "=f"(lo), "=f"(hi) : "l"(v));
}
__device__ __forceinline__ unsigned int redux_add_u32(unsigned int v) {
    unsigned int r;
    asm("redux.sync.add.u32 %0, %1, 0xffffffff;" : "=r"(r) : "r"(v));
    return r;
}

// smem union: gabor role needs t2 (132*17 u64 = 17952 B) + sgs (112*37 f =
// 16576 B) = 34528 B; cell role needs tile (7*18*19 f) + stot (7*16 f).
#define SMEM_BYTES (17952 + 16608)

// =====================================================================
// Mega kernel: grid (14, B), 224 threads.
//   blockIdx.x in [0,7)  -> cell role  (cy = blockIdx.x)
//   blockIdx.x in [7,14) -> gabor role (cx = blockIdx.x - 7), computes
//                           gray itself from RGB (no dependency on cell)
// =====================================================================
__global__ void __launch_bounds__(224, 4) mega(const float* __restrict__ img,
                                               const float* __restrict__ gk0,
                                               const float* __restrict__ gk1,
                                               float* __restrict__ out)
{
    __shared__ __align__(16) char smraw[SMEM_BYTES];

    const int b    = blockIdx.y;
    const int tid  = threadIdx.x;
    const int lane = tid & 31;
    const float* base = img + (size_t)b * 3 * NPIX;
    float* ob = out + (size_t)b * NFEAT;

    if (blockIdx.x < 7) {
        // =============================================================
        // CELL ROLE: warp-per-cell, 7 warps = 7 cell cols of row cy
        // =============================================================
        float (*tile)[18][19] = reinterpret_cast<float (*)[18][19]>(smraw);
        float (*stot)[16] = reinterpret_cast<float (*)[16]>(smraw + 7 * 18 * 19 * 4);

        const int cy   = blockIdx.x;
        const int cx   = tid >> 5;
        const int cell = cy * GRID + cx;

        const int oy = cy * 16 - 1;
        const int ox = cx * 16 - 1;
        const int cg  = lane & 3;
        const int rp  = lane >> 2;
        const int gx0 = cx * 16 + cg * 4;
        const int r0  = rp * 2;
        const int gy0 = cy * 16 + r0;

        float (*tw)[19] = tile[cx];

        float acc[15];
        #pragma unroll
        for (int k = 0; k < 15; k++) acc[k] = 0.0f;
        unsigned int hR = 0, hG = 0, hB = 0;

        #pragma unroll
        for (int q = 0; q < 2; q++) {
            const int p = (gy0 + q) * WW + gx0;
            float4 r4 = *reinterpret_cast<const float4*>(base + p);
            float4 g4 = *reinterpret_cast<const float4*>(base + NPIX + p);
            float4 b4 = *reinterpret_cast<const float4*>(base + 2 * NPIX + p);
            float R[4]  = {r4.x, r4.y, r4.z, r4.w};
            float Gc[4] = {g4.x, g4.y, g4.z, g4.w};
            float Bl[4] = {b4.x, b4.y, b4.z, b4.w};

            #pragma unroll
            for (int j = 0; j < 4; j++)
                tw[r0 + 1 + q][cg * 4 + 1 + j] =
                    0.299f * R[j] + 0.587f * Gc[j] + 0.114f * Bl[j];

            #pragma unroll
            for (int j = 0; j < 4; j++) {
                const float rr = R[j], gg = Gc[j], bb = Bl[j];
                int ir = __float2int_rd(rr * 8.0f); if ((unsigned)ir < 8u) hR += 1u << (ir << 2);
                int ig = __float2int_rd(gg * 8.0f); if ((unsigned)ig < 8u) hG += 1u << (ig << 2);
                int ib = __float2int_rd(bb * 8.0f); if ((unsigned)ib < 8u) hB += 1u << (ib << 2);

                float maxc = fmaxf(rr, fmaxf(gg, bb));
                float minc = fminf(rr, fminf(gg, bb));
                float vv = maxc;
                float delta = maxc - minc;
                float dsafe = (delta == 0.0f) ? 1.0f : delta;
                float me = maxc + 1e-8f;
                float inv = __fdividef(1.0f, me * dsafe);
                float ss = delta * dsafe * inv;
                float invd = me * inv;
                float rc = (maxc - rr) * invd;
                float gc = (maxc - gg) * invd;
                float bc = (maxc - bb) * invd;
                float hh;
                if (maxc == rr)      hh = bc - gc;
                else if (maxc == gg) hh = 2.0f + rc - bc;
                else                 hh = 4.0f + gc - rc;
                hh = hh * (1.0f / 6.0f);
                hh = hh - floorf(hh);
                hh = hh * TWO_PI_F;

                acc[0] += rr; acc[1] += gg; acc[2] += bb;
                acc[3] += hh; acc[4] += ss; acc[5] += vv;
                acc[6] += hh * hh; acc[7] += ss * ss; acc[8] += vv * vv;
            }
        }

        // halo: 68 perimeter positions (clamp == edge pad)
        for (int i = lane; i < 68; i += 32) {
            int rr, cc;
            if (i < 18)      { rr = 0;          cc = i; }
            else if (i < 36) { rr = 17;         cc = i - 18; }
            else if (i < 52) { rr = i - 36 + 1; cc = 0; }
            else             { rr = i - 52 + 1; cc = 17; }
            int yy = min(max(oy + rr, 0), HH - 1);
            int xx = min(max(ox + cc, 0), WW - 1);
            int pp = yy * WW + xx;
            tw[rr][cc] = 0.299f * base[pp] + 0.587f * base[NPIX + pp] + 0.114f * base[2 * NPIX + pp];
        }
        __syncwarp();

        // Sobel (clamp via halo) + Laplacian (reflect)
        {
            float w[4][6];
            #pragma unroll
            for (int i = 0; i < 4; i++)
                #pragma unroll
                for (int c = 0; c < 6; c++)
                    w[i][c] = tw[r0 + i][cg * 4 + c];

            const bool eL = (gx0 == 0), eR = (gx0 == WW - 4);
            #pragma unroll
            for (int k = 0; k < 2; k++) {
                const int gy = gy0 + k;
                const bool eT = (gy == 0), eB = (gy == HH - 1);
                float colS[6], dd[6], lapTB[6];
                #pragma unroll
                for (int c = 0; c < 6; c++) {
                    colS[c]  = w[k][c] + 2.0f * w[k+1][c] + w[k+2][c];
                    dd[c]    = w[k+2][c] - w[k][c];
                    lapTB[c] = (eT ? w[k+2][c] : w[k][c]) + (eB ? w[k][c] : w[k+2][c]);
                }
                #pragma unroll
                for (int j = 0; j < 4; j++) {
                    float gxv = 0.125f * (colS[j + 2] - colS[j]);
                    float gyv = 0.125f * (dd[j] + 2.0f * dd[j + 1] + dd[j + 2]);
                    float d2  = gxv * gxv + gyv * gyv;
                    float mag = sqrtf(d2 + 1e-8f);
                    float ca  = (d2 > 0.0f) ? gxv * rsqrtf(d2) : 1.0f;

                    float vL  = (eL && j == 0) ? lapTB[j + 2] : lapTB[j];
                    float w1L = (eL && j == 0) ? w[k+1][j + 2] : w[k+1][j];
                    float vR  = (eR && j == 3) ? lapTB[j] : lapTB[j + 2];
                    float w1R = (eR && j == 3) ? w[k+1][j] : w[k+1][j + 2];
                    float nb  = vL + lapTB[j + 1] + vR + w1L + w1R;
                    float lap = nb * 0.0625f - 0.5f * w[k+1][j + 1];

                    acc[9]  += mag; acc[10] += mag * mag; acc[11] += ca;
                    acc[12] += lap; acc[13] += lap * lap; acc[14] += fabsf(lap);
                }
            }
        }

        // histogram: nibble -> 16-bit fields -> redux
        unsigned int h16[12];
        h16[0] = (hR & 0xFu)         | ((hR << 12) & 0xF0000u);
        h16[1] = ((hR >> 8)  & 0xFu) | ((hR << 4)  & 0xF0000u);
        h16[2] = ((hR >> 16) & 0xFu) | ((hR >> 4)  & 0xF0000u);
        h16[3] = ((hR >> 24) & 0xFu) | ((hR >> 12) & 0xF0000u);
        h16[4] = (hG & 0xFu)         | ((hG << 12) & 0xF0000u);
        h16[5] = ((hG >> 8)  & 0xFu) | ((hG << 4)  & 0xF0000u);
        h16[6] = ((hG >> 16) & 0xFu) | ((hG >> 4)  & 0xF0000u);
        h16[7] = ((hG >> 24) & 0xFu) | ((hG >> 12) & 0xF0000u);
        h16[8] = (hB & 0xFu)         | ((hB << 12) & 0xF0000u);
        h16[9] = ((hB >> 8)  & 0xFu) | ((hB << 4)  & 0xF0000u);
        h16[10]= ((hB >> 16) & 0xFu) | ((hB >> 4)  & 0xF0000u);
        h16[11]= ((hB >> 24) & 0xFu) | ((hB >> 12) & 0xF0000u);
        #pragma unroll
        for (int k = 0; k < 12; k++) h16[k] = redux_add_u32(h16[k]);

        if (lane < 24) {
            unsigned int pick = 0;
            #pragma unroll
            for (int j = 0; j < 12; j++)
                if ((lane >> 1) == j) pick = h16[j];
            unsigned int cnt = (pick >> (16 * (lane & 1))) & 0xFFFFu;
            ob[3 + ((size_t)cell * 3 + (lane >> 3)) * 8 + (lane & 7)] = (float)cnt * (1.0f / 256.0f);
        }

        #pragma unroll
        for (int k = 0; k < 15; k++) {
            float x = acc[k];
            #pragma unroll
            for (int o = 16; o > 0; o >>= 1) x += __shfl_down_sync(0xffffffffu, x, o);
            if (lane == 0) stot[cx][k] = x;
        }
        __syncwarp();

        if (lane < 9) d_part[((size_t)b * NCELL + cell) * 9 + lane] = stot[cx][lane];
        if (lane >= 9 && lane < 12) ob[1185 + cell * 3 + (lane - 9)] = stot[cx][lane - 6] * (1.0f / 256.0f);
        if (lane == 12) {
            float sm = stot[cx][9], sq = stot[cx][10];
            ob[1332 + cell * 4 + 0] = sm * (1.0f / 256.0f);
            ob[1332 + cell * 4 + 1] = sqrtf(fmaxf(0.0f, (sq - sm * sm * (1.0f / 256.0f)) * (1.0f / 255.0f)));
            ob[1332 + cell * 4 + 2] = sq * (1.0f / 256.0f);
            ob[1332 + cell * 4 + 3] = stot[cx][11] * (1.0f / 256.0f);
        }
        if (lane == 13) {
            float lm = stot[cx][12], lq = stot[cx][13];
            ob[1528 + cell * 4 + 0] = lm * (1.0f / 256.0f);
            ob[1528 + cell * 4 + 1] = sqrtf(fmaxf(0.0f, (lq - lm * lm * (1.0f / 256.0f)) * (1.0f / 255.0f)));
            ob[1528 + cell * 4 + 2] = lq * (1.0f / 256.0f);
            ob[1528 + cell * 4 + 3] = stot[cx][14] * (1.0f / 256.0f);
        }
    } else {
        // =============================================================
        // GABOR ROLE: strip-fused both separable passes; computes gray
        // from RGB itself (no dependency on the cell role)
        // =============================================================
        unsigned long long* t2 = reinterpret_cast<unsigned long long*>(smraw);          // 132*17 u64
        float* sgs = reinterpret_cast<float*>(smraw + 132 * 17 * 8);                    // 112*37 f

        const int cx = blockIdx.x - 7;
        const int x0 = cx * 16;

        unsigned long long tapH[21];
        #pragma unroll
        for (int d = 0; d < 21; d++)
            tapH[d] = pk2(__ldg(&gk0[210 + d]), __ldg(&gk1[210 + d]));

        // zero t2 halo rows (0..9, 122..131)
        for (int i = tid; i < 20 * 16; i += 224) {
            int rr = i >> 4, cc = i & 15;
            int row = (rr < 10) ? rr : rr + 112;
            t2[row * 17 + cc] = 0ULL;
        }
        // gray strip from RGB: cols x0-10 .. x0+25, zero outside image
        for (int i = tid; i < 112 * 36; i += 224) {
            int row = i / 36, lc = i % 36;
            int gx = x0 - 10 + lc;
            float v = 0.0f;
            if (gx >= 0 && gx < WW) {
                int p = row * WW + gx;
                v = 0.299f * base[p] + 0.587f * base[NPIX + p] + 0.114f * base[2 * NPIX + p];
            }
            sgs[row * 37 + lc] = v;
        }
        __syncthreads();

        // h-pass: thread = (row, half); 8 outputs each
        {
            const int row  = (tid < 112) ? tid : tid - 112;
            const int j0   = (tid < 112) ? 0 : 8;
            const float* bp = sgs + row * 37 + j0;
            unsigned long long a[8];
            #pragma unroll
            for (int i = 0; i < 8; i++) a[i] = 0ULL;
            #pragma unroll
            for (int k = 0; k < 28; k++) {
                float v = bp[k];
                unsigned long long vp = pk2(v, v);
                #pragma unroll
                for (int i = 0; i < 8; i++) {
                    int d = k - i;
                    if (d >= 0 && d < 21) a[i] = fma2(tapH[d], vp, a[i]);
                }
            }
            unsigned long long* o = t2 + (row + 10) * 17 + j0;
            #pragma unroll
            for (int i = 0; i < 8; i++) o[i] = a[i];
        }

        unsigned long long tapV[21];
        {
            float inv0 = __fdividef(1.0f, __ldg(&gk0[220]));
            float inv1 = __fdividef(1.0f, __ldg(&gk1[220]));
            #pragma unroll
            for (int d = 0; d < 21; d++)
                tapV[d] = pk2(__ldg(&gk0[d * 21 + 10]) * inv0,
                              __ldg(&gk1[d * 21 + 10]) * inv1);
        }
        __syncthreads();

        // v-pass: 16 cols x 14 y-groups of 8; warp w == cell row w
        const int x = tid & 15, ty = tid >> 4, yb = ty * 8;
        unsigned long long a[8];
        #pragma unroll
        for (int j = 0; j < 8; j++) a[j] = 0ULL;
        #pragma unroll
        for (int k = 0; k < 28; k++) {
            unsigned long long vp = t2[(yb + k) * 17 + x];
            #pragma unroll
            for (int j = 0; j < 8; j++) {
                int d = k - j;
                if (d >= 0 && d < 21) a[j] = fma2(tapV[d], vp, a[j]);
            }
        }
        float s0 = 0.0f, s1 = 0.0f;
        #pragma unroll
        for (int j = 0; j < 8; j++) {
            float lo, hi;
            upk2(a[j], lo, hi);
            s0 += fabsf(lo);
            s1 += fabsf(hi);
        }
        #pragma unroll
        for (int o = 16; o > 0; o >>= 1) {
            s0 += __shfl_down_sync(0xffffffffu, s0, o);
            s1 += __shfl_down_sync(0xffffffffu, s1, o);
        }
        if (lane == 0) {
            int w = tid >> 5;             // cell row
            ob[1724 + w * GRID + cx] = s0 * (1.0f / 256.0f);
            ob[1773 + w * GRID + cx] = s1 * (1.0f / 256.0f);
        }
    }
}

// =====================================================================
// finalize: per-image channel means + HSV mean/std (ddof=1)
// =====================================================================
__global__ void finalize(float* __restrict__ out)
{
    __shared__ float fin[9];
    const int b = blockIdx.x;
    const int t = threadIdx.x;
    if (t < 9) {
        const float* pp = d_part + (size_t)b * NCELL * 9;
        float s = 0.0f;
        for (int c = 0; c < NCELL; c++) s += pp[c * 9 + t];
        fin[t] = s;
    }
    __syncwarp();
    if (t == 0) {
        float* ob = out + (size_t)b * NFEAT;
        const float N = (float)NPIX;
        ob[0] = fin[0] / N;
        ob[1] = fin[1] / N;
        ob[2] = fin[2] / N;
        #pragma unroll
        for (int k = 0; k < 3; k++) {
            float smv = fin[3 + k];
            float sqv = fin[6 + k];
            float var = (sqv - smv * smv / N) / (N - 1.0f);
            ob[1179 + 2 * k] = smv / N;
            ob[1180 + 2 * k] = sqrtf(fmaxf(var, 0.0f));
        }
    }
}

// =====================================================================
extern "C" void kernel_launch(void* const* d_in, const int* in_sizes, int n_in,
                              void* d_out, int out_size)
{
    const float* img = (const float*)d_in[0];
    const float* gk0 = (const float*)d_in[1];
    const float* gk1 = (const float*)d_in[2];
    float* out = (float*)d_out;

    int B = in_sizes[0] / (3 * NPIX);
    if (B > BMAX) B = BMAX;

    mega<<<dim3(14, B), 224>>>(img, gk0, gk1, out);
    finalize<<<B, 32>>>(out);
}

// round 16
// speedup vs baseline: 1.2678x; 1.0765x over previous
#include <cuda_runtime.h>
#include <math.h>

#define HH 112
#define WW 112
#define NPIX (HH*WW)          // 12544
#define GRID 7
#define NCELL 49
#define NFEAT 1822
#define BMAX 1024
#define TWO_PI_F 6.283185307179586f

// ---- scratch (static device arrays; no cudaMalloc anywhere) ----
__device__ float d_part[(size_t)BMAX * NCELL * 9];

// ---- f32x2 packed helpers (sm_100+) ----
__device__ __forceinline__ unsigned long long pk2(float a, float b) {
    unsigned long long r;
    asm("mov.b64 %0, {%1, %2};" : "=l"(r) : "f"(a), "f"(b));
    return r;
}
__device__ __forceinline__ unsigned long long fma2(unsigned long long a,
                                                   unsigned long long b,
                                                   unsigned long long c) {
    unsigned long long d;
    asm("fma.rn.f32x2 %0, %1, %2, %3;" : "=l"(d) : "l"(a), "l"(b), "l"(c));
    return d;
}
__device__ __forceinline__ void upk2(unsigned long long v, float& lo, float& hi) {
    asm("mov.b64 {%0, %1}, %2;" : "=f"(lo), "=f"(hi) : "l"(v));
}
__device__ __forceinline__ unsigned int redux_add_u32(unsigned int v) {
    unsigned int r;
    asm("redux.sync.add.u32 %0, %1, 0xffffffff;" : "=r"(r) : "r"(v));
    return r;
}

// smem union: gabor role needs t2 (132*17 u64 = 17952 B) + sgs (112*37 f =
// 16576 B) = 34528 B; cell role needs tile (7*18*19 f) + stot (7*16 f).
#define SMEM_BYTES (17952 + 16608)

// =====================================================================
// Mega kernel: grid (14, B), 224 threads, 5 blocks/SM.
//   blockIdx.x in [0,7)  -> cell role  (cy = blockIdx.x)
//   blockIdx.x in [7,14) -> gabor role (cx = blockIdx.x - 7), computes
//                           gray itself from RGB (no dependency on cell)
// Gabor taps are exactly even (tap[d] == tap[20-d]) -> store only 11
// packed taps per phase; index remap folds at compile time.
// =====================================================================
__global__ void __launch_bounds__(224, 5) mega(const float* __restrict__ img,
                                               const float* __restrict__ gk0,
                                               const float* __restrict__ gk1,
                                               float* __restrict__ out)
{
    __shared__ __align__(16) char smraw[SMEM_BYTES];

    const int b    = blockIdx.y;
    const int tid  = threadIdx.x;
    const int lane = tid & 31;
    const float* base = img + (size_t)b * 3 * NPIX;
    float* ob = out + (size_t)b * NFEAT;

    if (blockIdx.x < 7) {
        // =============================================================
        // CELL ROLE: warp-per-cell, 7 warps = 7 cell cols of row cy
        // =============================================================
        float (*tile)[18][19] = reinterpret_cast<float (*)[18][19]>(smraw);
        float (*stot)[16] = reinterpret_cast<float (*)[16]>(smraw + 7 * 18 * 19 * 4);

        const int cy   = blockIdx.x;
        const int cx   = tid >> 5;
        const int cell = cy * GRID + cx;

        const int oy = cy * 16 - 1;
        const int ox = cx * 16 - 1;
        const int cg  = lane & 3;
        const int rp  = lane >> 2;
        const int gx0 = cx * 16 + cg * 4;
        const int r0  = rp * 2;
        const int gy0 = cy * 16 + r0;

        float (*tw)[19] = tile[cx];

        float acc[15];
        #pragma unroll
        for (int k = 0; k < 15; k++) acc[k] = 0.0f;
        unsigned int hR = 0, hG = 0, hB = 0;

        #pragma unroll
        for (int q = 0; q < 2; q++) {
            const int p = (gy0 + q) * WW + gx0;
            float4 r4 = *reinterpret_cast<const float4*>(base + p);
            float4 g4 = *reinterpret_cast<const float4*>(base + NPIX + p);
            float4 b4 = *reinterpret_cast<const float4*>(base + 2 * NPIX + p);
            float R[4]  = {r4.x, r4.y, r4.z, r4.w};
            float Gc[4] = {g4.x, g4.y, g4.z, g4.w};
            float Bl[4] = {b4.x, b4.y, b4.z, b4.w};

            #pragma unroll
            for (int j = 0; j < 4; j++)
                tw[r0 + 1 + q][cg * 4 + 1 + j] =
                    0.299f * R[j] + 0.587f * Gc[j] + 0.114f * Bl[j];

            #pragma unroll
            for (int j = 0; j < 4; j++) {
                const float rr = R[j], gg = Gc[j], bb = Bl[j];
                int ir = __float2int_rd(rr * 8.0f); if ((unsigned)ir < 8u) hR += 1u << (ir << 2);
                int ig = __float2int_rd(gg * 8.0f); if ((unsigned)ig < 8u) hG += 1u << (ig << 2);
                int ib = __float2int_rd(bb * 8.0f); if ((unsigned)ib < 8u) hB += 1u << (ib << 2);

                float maxc = fmaxf(rr, fmaxf(gg, bb));
                float minc = fminf(rr, fminf(gg, bb));
                float vv = maxc;
                float delta = maxc - minc;
                float dsafe = (delta == 0.0f) ? 1.0f : delta;
                float me = maxc + 1e-8f;
                float inv = __fdividef(1.0f, me * dsafe);
                float ss = delta * dsafe * inv;
                float invd = me * inv;
                float rc = (maxc - rr) * invd;
                float gc = (maxc - gg) * invd;
                float bc = (maxc - bb) * invd;
                float hh;
                if (maxc == rr)      hh = bc - gc;
                else if (maxc == gg) hh = 2.0f + rc - bc;
                else                 hh = 4.0f + gc - rc;
                hh = hh * (1.0f / 6.0f);
                hh = hh - floorf(hh);
                hh = hh * TWO_PI_F;

                acc[0] += rr; acc[1] += gg; acc[2] += bb;
                acc[3] += hh; acc[4] += ss; acc[5] += vv;
                acc[6] += hh * hh; acc[7] += ss * ss; acc[8] += vv * vv;
            }
        }

        // halo: 68 perimeter positions (clamp == edge pad)
        for (int i = lane; i < 68; i += 32) {
            int rr, cc;
            if (i < 18)      { rr = 0;          cc = i; }
            else if (i < 36) { rr = 17;         cc = i - 18; }
            else if (i < 52) { rr = i - 36 + 1; cc = 0; }
            else             { rr = i - 52 + 1; cc = 17; }
            int yy = min(max(oy + rr, 0), HH - 1);
            int xx = min(max(ox + cc, 0), WW - 1);
            int pp = yy * WW + xx;
            tw[rr][cc] = 0.299f * base[pp] + 0.587f * base[NPIX + pp] + 0.114f * base[2 * NPIX + pp];
        }
        __syncwarp();

        // Sobel (clamp via halo) + Laplacian (reflect)
        {
            float w[4][6];
            #pragma unroll
            for (int i = 0; i < 4; i++)
                #pragma unroll
                for (int c = 0; c < 6; c++)
                    w[i][c] = tw[r0 + i][cg * 4 + c];

            const bool eL = (gx0 == 0), eR = (gx0 == WW - 4);
            #pragma unroll
            for (int k = 0; k < 2; k++) {
                const int gy = gy0 + k;
                const bool eT = (gy == 0), eB = (gy == HH - 1);
                float colS[6], dd[6], lapTB[6];
                #pragma unroll
                for (int c = 0; c < 6; c++) {
                    colS[c]  = w[k][c] + 2.0f * w[k+1][c] + w[k+2][c];
                    dd[c]    = w[k+2][c] - w[k][c];
                    lapTB[c] = (eT ? w[k+2][c] : w[k][c]) + (eB ? w[k][c] : w[k+2][c]);
                }
                #pragma unroll
                for (int j = 0; j < 4; j++) {
                    float gxv = 0.125f * (colS[j + 2] - colS[j]);
                    float gyv = 0.125f * (dd[j] + 2.0f * dd[j + 1] + dd[j + 2]);
                    float d2  = gxv * gxv + gyv * gyv;
                    float mag = sqrtf(d2 + 1e-8f);
                    float ca  = (d2 > 0.0f) ? gxv * rsqrtf(d2) : 1.0f;

                    float vL  = (eL && j == 0) ? lapTB[j + 2] : lapTB[j];
                    float w1L = (eL && j == 0) ? w[k+1][j + 2] : w[k+1][j];
                    float vR  = (eR && j == 3) ? lapTB[j] : lapTB[j + 2];
                    float w1R = (eR && j == 3) ? w[k+1][j] : w[k+1][j + 2];
                    float nb  = vL + lapTB[j + 1] + vR + w1L + w1R;
                    float lap = nb * 0.0625f - 0.5f * w[k+1][j + 1];

                    acc[9]  += mag; acc[10] += mag * mag; acc[11] += ca;
                    acc[12] += lap; acc[13] += lap * lap; acc[14] += fabsf(lap);
                }
            }
        }

        // histogram: nibble -> 16-bit fields -> redux
        unsigned int h16[12];
        h16[0] = (hR & 0xFu)         | ((hR << 12) & 0xF0000u);
        h16[1] = ((hR >> 8)  & 0xFu) | ((hR << 4)  & 0xF0000u);
        h16[2] = ((hR >> 16) & 0xFu) | ((hR >> 4)  & 0xF0000u);
        h16[3] = ((hR >> 24) & 0xFu) | ((hR >> 12) & 0xF0000u);
        h16[4] = (hG & 0xFu)         | ((hG << 12) & 0xF0000u);
        h16[5] = ((hG >> 8)  & 0xFu) | ((hG << 4)  & 0xF0000u);
        h16[6] = ((hG >> 16) & 0xFu) | ((hG >> 4)  & 0xF0000u);
        h16[7] = ((hG >> 24) & 0xFu) | ((hG >> 12) & 0xF0000u);
        h16[8] = (hB & 0xFu)         | ((hB << 12) & 0xF0000u);
        h16[9] = ((hB >> 8)  & 0xFu) | ((hB << 4)  & 0xF0000u);
        h16[10]= ((hB >> 16) & 0xFu) | ((hB >> 4)  & 0xF0000u);
        h16[11]= ((hB >> 24) & 0xFu) | ((hB >> 12) & 0xF0000u);
        #pragma unroll
        for (int k = 0; k < 12; k++) h16[k] = redux_add_u32(h16[k]);

        if (lane < 24) {
            unsigned int pick = 0;
            #pragma unroll
            for (int j = 0; j < 12; j++)
                if ((lane >> 1) == j) pick = h16[j];
            unsigned int cnt = (pick >> (16 * (lane & 1))) & 0xFFFFu;
            ob[3 + ((size_t)cell * 3 + (lane >> 3)) * 8 + (lane & 7)] = (float)cnt * (1.0f / 256.0f);
        }

        #pragma unroll
        for (int k = 0; k < 15; k++) {
            float x = acc[k];
            #pragma unroll
            for (int o = 16; o > 0; o >>= 1) x += __shfl_down_sync(0xffffffffu, x, o);
            if (lane == 0) stot[cx][k] = x;
        }
        __syncwarp();

        if (lane < 9) d_part[((size_t)b * NCELL + cell) * 9 + lane] = stot[cx][lane];
        if (lane >= 9 && lane < 12) ob[1185 + cell * 3 + (lane - 9)] = stot[cx][lane - 6] * (1.0f / 256.0f);
        if (lane == 12) {
            float sm = stot[cx][9], sq = stot[cx][10];
            ob[1332 + cell * 4 + 0] = sm * (1.0f / 256.0f);
            ob[1332 + cell * 4 + 1] = sqrtf(fmaxf(0.0f, (sq - sm * sm * (1.0f / 256.0f)) * (1.0f / 255.0f)));
            ob[1332 + cell * 4 + 2] = sq * (1.0f / 256.0f);
            ob[1332 + cell * 4 + 3] = stot[cx][11] * (1.0f / 256.0f);
        }
        if (lane == 13) {
            float lm = stot[cx][12], lq = stot[cx][13];
            ob[1528 + cell * 4 + 0] = lm * (1.0f / 256.0f);
            ob[1528 + cell * 4 + 1] = sqrtf(fmaxf(0.0f, (lq - lm * lm * (1.0f / 256.0f)) * (1.0f / 255.0f)));
            ob[1528 + cell * 4 + 2] = lq * (1.0f / 256.0f);
            ob[1528 + cell * 4 + 3] = stot[cx][14] * (1.0f / 256.0f);
        }
    } else {
        // =============================================================
        // GABOR ROLE: strip-fused separable passes; symmetric taps
        // (tap[d] == tap[20-d]) -> 11 packed taps per phase.
        // =============================================================
        unsigned long long* t2 = reinterpret_cast<unsigned long long*>(smraw);          // 132*17 u64
        float* sgs = reinterpret_cast<float*>(smraw + 132 * 17 * 8);                    // 112*37 f

        const int cx = blockIdx.x - 7;
        const int x0 = cx * 16;

        unsigned long long tapH[11];
        #pragma unroll
        for (int d = 0; d < 11; d++)
            tapH[d] = pk2(__ldg(&gk0[210 + d]), __ldg(&gk1[210 + d]));

        // zero t2 halo rows (0..9, 122..131)
        for (int i = tid; i < 20 * 16; i += 224) {
            int rr = i >> 4, cc = i & 15;
            int row = (rr < 10) ? rr : rr + 112;
            t2[row * 17 + cc] = 0ULL;
        }
        // gray strip from RGB: cols x0-10 .. x0+25, zero outside image
        for (int i = tid; i < 112 * 36; i += 224) {
            int row = i / 36, lc = i % 36;
            int gx = x0 - 10 + lc;
            float v = 0.0f;
            if (gx >= 0 && gx < WW) {
                int p = row * WW + gx;
                v = 0.299f * base[p] + 0.587f * base[NPIX + p] + 0.114f * base[2 * NPIX + p];
            }
            sgs[row * 37 + lc] = v;
        }
        __syncthreads();

        // h-pass: thread = (row, half); 8 outputs each
        {
            const int row  = (tid < 112) ? tid : tid - 112;
            const int j0   = (tid < 112) ? 0 : 8;
            const float* bp = sgs + row * 37 + j0;
            unsigned long long a[8];
            #pragma unroll
            for (int i = 0; i < 8; i++) a[i] = 0ULL;
            #pragma unroll
            for (int k = 0; k < 28; k++) {
                float v = bp[k];
                unsigned long long vp = pk2(v, v);
                #pragma unroll
                for (int i = 0; i < 8; i++) {
                    int d = k - i;
                    if (d >= 0 && d < 21) {
                        int ds = (d < 11) ? d : 20 - d;   // symmetric tap remap
                        a[i] = fma2(tapH[ds], vp, a[i]);
                    }
                }
            }
            unsigned long long* o = t2 + (row + 10) * 17 + j0;
            #pragma unroll
            for (int i = 0; i < 8; i++) o[i] = a[i];
        }

        unsigned long long tapV[11];
        {
            float inv0 = __fdividef(1.0f, __ldg(&gk0[220]));
            float inv1 = __fdividef(1.0f, __ldg(&gk1[220]));
            #pragma unroll
            for (int d = 0; d < 11; d++)
                tapV[d] = pk2(__ldg(&gk0[d * 21 + 10]) * inv0,
                              __ldg(&gk1[d * 21 + 10]) * inv1);
        }
        __syncthreads();

        // v-pass: 16 cols x 14 y-groups of 8; warp w == cell row w
        const int x = tid & 15, ty = tid >> 4, yb = ty * 8;
        unsigned long long a[8];
        #pragma unroll
        for (int j = 0; j < 8; j++) a[j] = 0ULL;
        #pragma unroll
        for (int k = 0; k < 28; k++) {
            unsigned long long vp = t2[(yb + k) * 17 + x];
            #pragma unroll
            for (int j = 0; j < 8; j++) {
                int d = k - j;
                if (d >= 0 && d < 21) {
                    int ds = (d < 11) ? d : 20 - d;       // symmetric tap remap
                    a[j] = fma2(tapV[ds], vp, a[j]);
                }
            }
        }
        float s0 = 0.0f, s1 = 0.0f;
        #pragma unroll
        for (int j = 0; j < 8; j++) {
            float lo, hi;
            upk2(a[j], lo, hi);
            s0 += fabsf(lo);
            s1 += fabsf(hi);
        }
        #pragma unroll
        for (int o = 16; o > 0; o >>= 1) {
            s0 += __shfl_down_sync(0xffffffffu, s0, o);
            s1 += __shfl_down_sync(0xffffffffu, s1, o);
        }
        if (lane == 0) {
            int w = tid >> 5;             // cell row
            ob[1724 + w * GRID + cx] = s0 * (1.0f / 256.0f);
            ob[1773 + w * GRID + cx] = s1 * (1.0f / 256.0f);
        }
    }
}

// =====================================================================
// finalize: per-image channel means + HSV mean/std (ddof=1)
// =====================================================================
__global__ void finalize(float* __restrict__ out)
{
    __shared__ float fin[9];
    const int b = blockIdx.x;
    const int t = threadIdx.x;
    if (t < 9) {
        const float* pp = d_part + (size_t)b * NCELL * 9;
        float s = 0.0f;
        for (int c = 0; c < NCELL; c++) s += pp[c * 9 + t];
        fin[t] = s;
    }
    __syncwarp();
    if (t == 0) {
        float* ob = out + (size_t)b * NFEAT;
        const float N = (float)NPIX;
        ob[0] = fin[0] / N;
        ob[1] = fin[1] / N;
        ob[2] = fin[2] / N;
        #pragma unroll
        for (int k = 0; k < 3; k++) {
            float smv = fin[3 + k];
            float sqv = fin[6 + k];
            float var = (sqv - smv * smv / N) / (N - 1.0f);
            ob[1179 + 2 * k] = smv / N;
            ob[1180 + 2 * k] = sqrtf(fmaxf(var, 0.0f));
        }
    }
}

// =====================================================================
extern "C" void kernel_launch(void* const* d_in, const int* in_sizes, int n_in,
                              void* d_out, int out_size)
{
    const float* img = (const float*)d_in[0];
    const float* gk0 = (const float*)d_in[1];
    const float* gk1 = (const float*)d_in[2];
    float* out = (float*)d_out;

    int B = in_sizes[0] / (3 * NPIX);
    if (B > BMAX) B = BMAX;

    mega<<<dim3(14, B), 224>>>(img, gk0, gk1, out);
    finalize<<<B, 32>>>(out);
}